// round 2
// baseline (speedup 1.0000x reference)
#include <cuda_runtime.h>
#include <cuda_bf16.h>
#include <cstdint>

#define B_   16384
#define T_   4
#define D_   1024
#define MROWS (B_*T_)
#define N1   (3*D_)

__device__ __nv_bfloat16 g_Xhi[(size_t)MROWS*D_];
__device__ __nv_bfloat16 g_Xlo[(size_t)MROWS*D_];
__device__ __nv_bfloat16 g_W1hi[(size_t)D_*N1];
__device__ __nv_bfloat16 g_W1lo[(size_t)D_*N1];
__device__ __nv_bfloat16 g_W2hi[(size_t)D_*D_];
__device__ __nv_bfloat16 g_W2lo[(size_t)D_*D_];
__device__ float         g_qkv[(size_t)MROWS*N1];
__device__ float         g_uq[(size_t)MROWS*8];
__device__ float         g_uv[(size_t)MROWS*8];
__device__ __nv_bfloat16 g_Mhi[(size_t)B_*D_];
__device__ __nv_bfloat16 g_Mlo[(size_t)B_*D_];
__device__ float         g_P[(size_t)B_*8];

__device__ __forceinline__ void bf16split(float v, __nv_bfloat16& h, __nv_bfloat16& l) {
    h = __float2bfloat16_rn(v);
    l = __float2bfloat16_rn(v - __bfloat162float(h));
}

__global__ void k_convert(const float* __restrict__ src,
                          __nv_bfloat16* __restrict__ hi,
                          __nv_bfloat16* __restrict__ lo, int n4) {
    int i = blockIdx.x * blockDim.x + threadIdx.x;
    if (i >= n4) return;
    float4 v = ((const float4*)src)[i];
    __nv_bfloat16 h0,h1,h2,h3,l0,l1,l2,l3;
    bf16split(v.x,h0,l0); bf16split(v.y,h1,l1);
    bf16split(v.z,h2,l2); bf16split(v.w,h3,l3);
    ((__nv_bfloat162*)hi)[2*i]   = __nv_bfloat162(h0,h1);
    ((__nv_bfloat162*)hi)[2*i+1] = __nv_bfloat162(h2,h3);
    ((__nv_bfloat162*)lo)[2*i]   = __nv_bfloat162(l0,l1);
    ((__nv_bfloat162*)lo)[2*i+1] = __nv_bfloat162(l2,l3);
}

__global__ void k_prepx(const float4* __restrict__ x, const float4* __restrict__ tp) {
    int i = blockIdx.x * 256 + threadIdx.x;
    int row = i >> 8;
    int d4  = i & 255;
    int t   = row & 3;
    float4 v = x[i];
    float4 p = tp[(t<<8) + d4];
    v.x += p.x; v.y += p.y; v.z += p.z; v.w += p.w;
    __nv_bfloat16 h0,h1,h2,h3,l0,l1,l2,l3;
    bf16split(v.x,h0,l0); bf16split(v.y,h1,l1);
    bf16split(v.z,h2,l2); bf16split(v.w,h3,l3);
    ((__nv_bfloat162*)g_Xhi)[2*i]   = __nv_bfloat162(h0,h1);
    ((__nv_bfloat162*)g_Xhi)[2*i+1] = __nv_bfloat162(h2,h3);
    ((__nv_bfloat162*)g_Xlo)[2*i]   = __nv_bfloat162(l0,l1);
    ((__nv_bfloat162*)g_Xlo)[2*i+1] = __nv_bfloat162(l2,l3);
}

__global__ void k_lorau(const float* __restrict__ x, const float* __restrict__ tp,
                        const float* __restrict__ Aq, const float* __restrict__ Av) {
    int w = threadIdx.x >> 5, lane = threadIdx.x & 31;
    int row = (blockIdx.x << 3) + w;
    int t = row & 3;
    const float* xr = x  + (size_t)row * D_;
    const float* tr = tp + (size_t)t   * D_;
    float pq[8] = {0,0,0,0,0,0,0,0};
    float pv[8] = {0,0,0,0,0,0,0,0};
    for (int d = lane; d < D_; d += 32) {
        float xv = xr[d] + tr[d];
        float4 a0 = *(const float4*)(Aq + d*8);
        float4 a1 = *(const float4*)(Aq + d*8 + 4);
        float4 b0 = *(const float4*)(Av + d*8);
        float4 b1 = *(const float4*)(Av + d*8 + 4);
        pq[0]+=xv*a0.x; pq[1]+=xv*a0.y; pq[2]+=xv*a0.z; pq[3]+=xv*a0.w;
        pq[4]+=xv*a1.x; pq[5]+=xv*a1.y; pq[6]+=xv*a1.z; pq[7]+=xv*a1.w;
        pv[0]+=xv*b0.x; pv[1]+=xv*b0.y; pv[2]+=xv*b0.z; pv[3]+=xv*b0.w;
        pv[4]+=xv*b1.x; pv[5]+=xv*b1.y; pv[6]+=xv*b1.z; pv[7]+=xv*b1.w;
    }
    #pragma unroll
    for (int off = 16; off > 0; off >>= 1)
        #pragma unroll
        for (int r = 0; r < 8; r++) {
            pq[r] += __shfl_xor_sync(0xffffffffu, pq[r], off);
            pv[r] += __shfl_xor_sync(0xffffffffu, pv[r], off);
        }
    if (lane == 0) {
        ((float4*)(g_uq + (size_t)row*8))[0] = make_float4(pq[0],pq[1],pq[2],pq[3]);
        ((float4*)(g_uq + (size_t)row*8))[1] = make_float4(pq[4],pq[5],pq[6],pq[7]);
        ((float4*)(g_uv + (size_t)row*8))[0] = make_float4(pv[0],pv[1],pv[2],pv[3]);
        ((float4*)(g_uv + (size_t)row*8))[1] = make_float4(pv[4],pv[5],pv[6],pv[7]);
    }
}

#define SMEM_BYTES 75776
__device__ __forceinline__ uint32_t sA(int buf, int hl, int row, int col) {
    return (uint32_t)(buf*20480 + hl*10240 + row*80 + col*2);
}
__device__ __forceinline__ uint32_t sB(int buf, int hl, int row, int col) {
    return (uint32_t)(40960 + buf*17408 + hl*8704 + row*272 + col*2);
}
#define CP16(dst, src) asm volatile("cp.async.cg.shared.global [%0], [%1], 16;\n" :: "r"(dst), "l"(src))
#define LDSM4(R, addr) asm volatile("ldmatrix.sync.aligned.m8n8.x4.shared.b16 {%0,%1,%2,%3}, [%4];\n" \
    : "=r"((R)[0]), "=r"((R)[1]), "=r"((R)[2]), "=r"((R)[3]) : "r"(addr))
#define LDSM2T(R, addr) asm volatile("ldmatrix.sync.aligned.m8n8.x2.trans.shared.b16 {%0,%1}, [%2];\n" \
    : "=r"((R)[0]), "=r"((R)[1]) : "r"(addr))
#define MMA16816(Dp, A, Bf) asm volatile( \
    "mma.sync.aligned.m16n8k16.row.col.f32.bf16.bf16.f32 {%0,%1,%2,%3},{%4,%5,%6,%7},{%8,%9},{%0,%1,%2,%3};\n" \
    : "+f"((Dp)[0]), "+f"((Dp)[1]), "+f"((Dp)[2]), "+f"((Dp)[3]) \
    : "r"((A)[0]), "r"((A)[1]), "r"((A)[2]), "r"((A)[3]), "r"((Bf)[0]), "r"((Bf)[1]))

template<bool EPI>
__global__ void __launch_bounds__(256) k_gemm(
    const __nv_bfloat16* __restrict__ Ahi, const __nv_bfloat16* __restrict__ Alo,
    const __nv_bfloat16* __restrict__ Bhi, const __nv_bfloat16* __restrict__ Blo,
    float* __restrict__ C, int N, int K,
    const float* __restrict__ bias, const float* __restrict__ P,
    const float* __restrict__ LB)
{
    extern __shared__ __align__(16) char smem[];
    uint32_t sb = (uint32_t)__cvta_generic_to_shared(smem);
    int tid = threadIdx.x;
    int bm = blockIdx.y << 7, bn = blockIdx.x << 7;
    int KT = K >> 5;

    float d[2][8][4];
    #pragma unroll
    for (int i = 0; i < 2; i++)
        #pragma unroll
        for (int j = 0; j < 8; j++) { d[i][j][0]=0.f; d[i][j][1]=0.f; d[i][j][2]=0.f; d[i][j][3]=0.f; }

    int w = tid >> 5, lane = tid & 31;
    int wm = w & 3, wn = w >> 2;
    int ar0 = tid >> 2, akc = (tid & 3) << 3;
    int br0 = tid >> 4, bnc = (tid & 15) << 3;

    auto load_stage = [&](int kt, int buf) {
        CP16(sb + sA(buf,0,ar0,    akc), Ahi + (size_t)(bm + ar0     ) * K + (kt<<5) + akc);
        CP16(sb + sA(buf,0,ar0+64, akc), Ahi + (size_t)(bm + ar0 + 64) * K + (kt<<5) + akc);
        CP16(sb + sA(buf,1,ar0,    akc), Alo + (size_t)(bm + ar0     ) * K + (kt<<5) + akc);
        CP16(sb + sA(buf,1,ar0+64, akc), Alo + (size_t)(bm + ar0 + 64) * K + (kt<<5) + akc);
        CP16(sb + sB(buf,0,br0,    bnc), Bhi + (size_t)((kt<<5) + br0     ) * N + bn + bnc);
        CP16(sb + sB(buf,0,br0+16, bnc), Bhi + (size_t)((kt<<5) + br0 + 16) * N + bn + bnc);
        CP16(sb + sB(buf,1,br0,    bnc), Blo + (size_t)((kt<<5) + br0     ) * N + bn + bnc);
        CP16(sb + sB(buf,1,br0+16, bnc), Blo + (size_t)((kt<<5) + br0 + 16) * N + bn + bnc);
        asm volatile("cp.async.commit_group;\n");
    };

    load_stage(0, 0);
    int sub = lane >> 3, rr = lane & 7;
    int blrow = lane & 15;

    for (int kt = 0; kt < KT; kt++) {
        asm volatile("cp.async.wait_group 0;\n" ::: "memory");
        __syncthreads();
        int buf = kt & 1;
        if (kt + 1 < KT) load_stage(kt + 1, buf ^ 1);
        #pragma unroll
        for (int ks = 0; ks < 2; ks++) {
            uint32_t ah[2][4], al[2][4];
            #pragma unroll
            for (int mt = 0; mt < 2; mt++) {
                int arow = (wm<<5) + (mt<<4) + ((sub&1)<<3) + rr;
                int acol = (ks<<4) + ((sub>>1)<<3);
                LDSM4(ah[mt], sb + sA(buf,0,arow,acol));
                LDSM4(al[mt], sb + sA(buf,1,arow,acol));
            }
            uint32_t bh[8][2], bl[8][2];
            int krow = (ks<<4) + blrow;
            #pragma unroll
            for (int nt = 0; nt < 8; nt++) {
                int bcol = (wn<<6) + (nt<<3);
                LDSM2T(bh[nt], sb + sB(buf,0,krow,bcol));
                LDSM2T(bl[nt], sb + sB(buf,1,krow,bcol));
            }
            #pragma unroll
            for (int mt = 0; mt < 2; mt++)
                #pragma unroll
                for (int nt = 0; nt < 8; nt++) {
                    MMA16816(d[mt][nt], ah[mt], bh[nt]);
                    MMA16816(d[mt][nt], ah[mt], bl[nt]);
                    MMA16816(d[mt][nt], al[mt], bh[nt]);
                }
        }
        __syncthreads();
    }

    int g = lane >> 2, tq = (lane & 3) << 1;
    #pragma unroll
    for (int mt = 0; mt < 2; mt++)
        #pragma unroll
        for (int e2 = 0; e2 < 2; e2++) {
            int row = bm + (wm<<5) + (mt<<4) + (e2<<3) + g;
            float p0=0,p1=0,p2=0,p3=0,p4=0,p5=0,p6=0,p7=0;
            if (EPI) {
                const float* pr = P + (size_t)row*8;
                p0=pr[0];p1=pr[1];p2=pr[2];p3=pr[3];
                p4=pr[4];p5=pr[5];p6=pr[6];p7=pr[7];
            }
            #pragma unroll
            for (int nt = 0; nt < 8; nt++) {
                int col = bn + (wn<<6) + (nt<<3) + tq;
                float v0 = d[mt][nt][e2*2], v1 = d[mt][nt][e2*2+1];
                if (EPI) {
                    v0 += bias[col] + 2.f*(p0*LB[col] + p1*LB[N+col] + p2*LB[2*N+col] + p3*LB[3*N+col]
                        + p4*LB[4*N+col] + p5*LB[5*N+col] + p6*LB[6*N+col] + p7*LB[7*N+col]);
                    v1 += bias[col+1] + 2.f*(p0*LB[col+1] + p1*LB[N+col+1] + p2*LB[2*N+col+1] + p3*LB[3*N+col+1]
                        + p4*LB[4*N+col+1] + p5*LB[5*N+col+1] + p6*LB[6*N+col+1] + p7*LB[7*N+col+1]);
                }
                float2 o; o.x = v0; o.y = v1;
                *(float2*)(C + (size_t)row*N + col) = o;
            }
        }
}

__global__ void __launch_bounds__(512) k_attn(const float* __restrict__ Bq,
                                              const float* __restrict__ Bv,
                                              const float* __restrict__ Apj) {
    __shared__ float pacc[8];
    int tid = threadIdx.x;
    if (tid < 8) pacc[tid] = 0.f;
    __syncthreads();
    int b = blockIdx.x;
    int h = tid >> 5, lane = tid & 31;
    int row0 = b << 2;
    int c0 = (h << 6) + lane;

    float q[4][2], k[4][2], v[4][2];
    #pragma unroll
    for (int t = 0; t < 4; t++) {
        size_t base = (size_t)(row0 + t) * 3072;
        const float* uqr = g_uq + (size_t)(row0 + t) * 8;
        const float* uvr = g_uv + (size_t)(row0 + t) * 8;
        float dq0=0, dq1=0, dv0=0, dv1=0;
        #pragma unroll
        for (int r = 0; r < 8; r++) {
            float uqv = uqr[r], uvv = uvr[r];
            dq0 += uqv * Bq[r*1024 + c0];
            dq1 += uqv * Bq[r*1024 + c0 + 32];
            dv0 += uvv * Bv[r*1024 + c0];
            dv1 += uvv * Bv[r*1024 + c0 + 32];
        }
        q[t][0] = g_qkv[base + c0]        + 2.f*dq0;
        q[t][1] = g_qkv[base + c0 + 32]   + 2.f*dq1;
        k[t][0] = g_qkv[base + 1024 + c0];
        k[t][1] = g_qkv[base + 1024 + c0 + 32];
        v[t][0] = g_qkv[base + 2048 + c0]      + 2.f*dv0;
        v[t][1] = g_qkv[base + 2048 + c0 + 32] + 2.f*dv1;
    }
    float sc[4][4];
    #pragma unroll
    for (int t = 0; t < 4; t++)
        #pragma unroll
        for (int s = 0; s < 4; s++) {
            float p = q[t][0]*k[s][0] + q[t][1]*k[s][1];
            #pragma unroll
            for (int off = 16; off > 0; off >>= 1)
                p += __shfl_xor_sync(0xffffffffu, p, off);
            sc[t][s] = p * 0.125f;
        }
    float a0 = 0.f, a1 = 0.f;
    #pragma unroll
    for (int t = 0; t < 4; t++) {
        float m = fmaxf(fmaxf(sc[t][0], sc[t][1]), fmaxf(sc[t][2], sc[t][3]));
        float e0 = __expf(sc[t][0]-m), e1 = __expf(sc[t][1]-m);
        float e2 = __expf(sc[t][2]-m), e3 = __expf(sc[t][3]-m);
        float inv = 1.f / (e0+e1+e2+e3);
        a0 += (e0*v[0][0] + e1*v[1][0] + e2*v[2][0] + e3*v[3][0]) * inv;
        a1 += (e0*v[0][1] + e1*v[1][1] + e2*v[2][1] + e3*v[3][1]) * inv;
    }
    a0 *= 0.25f; a1 *= 0.25f;
    size_t oi = (size_t)b*1024 + c0;
    __nv_bfloat16 hh, ll;
    bf16split(a0, hh, ll); g_Mhi[oi]    = hh; g_Mlo[oi]    = ll;
    bf16split(a1, hh, ll); g_Mhi[oi+32] = hh; g_Mlo[oi+32] = ll;
    float pp[8];
    #pragma unroll
    for (int r = 0; r < 8; r++)
        pp[r] = a0 * Apj[(size_t)c0*8 + r] + a1 * Apj[(size_t)(c0+32)*8 + r];
    #pragma unroll
    for (int off = 16; off > 0; off >>= 1)
        #pragma unroll
        for (int r = 0; r < 8; r++)
            pp[r] += __shfl_xor_sync(0xffffffffu, pp[r], off);
    if (lane == 0) {
        #pragma unroll
        for (int r = 0; r < 8; r++) atomicAdd(&pacc[r], pp[r]);
    }
    __syncthreads();
    if (tid < 8) g_P[(size_t)b*8 + tid] = pacc[tid];
}

extern "C" void kernel_launch(void* const* d_in, const int* in_sizes, int n_in,
                              void* d_out, int out_size) {
    const float* x    = (const float*)d_in[0];
    const float* tp   = (const float*)d_in[1];
    const float* Wqkv = (const float*)d_in[2];
    const float* lqA  = (const float*)d_in[3];
    const float* lqB  = (const float*)d_in[4];
    const float* lvA  = (const float*)d_in[5];
    const float* lvB  = (const float*)d_in[6];
    const float* Wp   = (const float*)d_in[7];
    const float* bp   = (const float*)d_in[8];
    const float* lpA  = (const float*)d_in[9];
    const float* lpB  = (const float*)d_in[10];
    float* out = (float*)d_out;

    static bool attr_set = false;
    if (!attr_set) {
        cudaFuncSetAttribute(k_gemm<false>, cudaFuncAttributeMaxDynamicSharedMemorySize, SMEM_BYTES);
        cudaFuncSetAttribute(k_gemm<true>,  cudaFuncAttributeMaxDynamicSharedMemorySize, SMEM_BYTES);
        attr_set = true;
    }

    void *pXhi, *pXlo, *pW1hi, *pW1lo, *pW2hi, *pW2lo, *pQkv, *pMhi, *pMlo, *pP;
    cudaGetSymbolAddress(&pXhi,  g_Xhi);  cudaGetSymbolAddress(&pXlo,  g_Xlo);
    cudaGetSymbolAddress(&pW1hi, g_W1hi); cudaGetSymbolAddress(&pW1lo, g_W1lo);
    cudaGetSymbolAddress(&pW2hi, g_W2hi); cudaGetSymbolAddress(&pW2lo, g_W2lo);
    cudaGetSymbolAddress(&pQkv,  g_qkv);
    cudaGetSymbolAddress(&pMhi,  g_Mhi);  cudaGetSymbolAddress(&pMlo,  g_Mlo);
    cudaGetSymbolAddress(&pP,    g_P);

    k_convert<<<3072, 256>>>(Wqkv, (__nv_bfloat16*)pW1hi, (__nv_bfloat16*)pW1lo, 786432);
    k_convert<<<1024, 256>>>(Wp,   (__nv_bfloat16*)pW2hi, (__nv_bfloat16*)pW2lo, 262144);
    k_prepx<<<65536, 256>>>((const float4*)x, (const float4*)tp);
    k_lorau<<<8192, 256>>>(x, tp, lqA, lvA);

    k_gemm<false><<<dim3(24, 512), 256, SMEM_BYTES>>>(
        (const __nv_bfloat16*)pXhi, (const __nv_bfloat16*)pXlo,
        (const __nv_bfloat16*)pW1hi, (const __nv_bfloat16*)pW1lo,
        (float*)pQkv, N1, D_, nullptr, nullptr, nullptr);

    k_attn<<<B_, 512>>>(lqB, lvB, lpA);

    k_gemm<true><<<dim3(8, 128), 256, SMEM_BYTES>>>(
        (const __nv_bfloat16*)pMhi, (const __nv_bfloat16*)pMlo,
        (const __nv_bfloat16*)pW2hi, (const __nv_bfloat16*)pW2lo,
        out, D_, D_, bp, (const float*)pP, lpB);
}